// round 2
// baseline (speedup 1.0000x reference)
#include <cuda_runtime.h>
#include <cuda_bf16.h>
#include <math.h>

// Problem constants
#define T_TOK   16384     // B*M = 8*2048
#define FEAT    1024      // seq_len1 = seq_len2 = H*Kd = H*Vd
#define NHEAD   16
#define KD      64
#define VD      64

// ---------------- scratch (no cudaMalloc allowed) ----------------
__device__ float g_Q[(size_t)T_TOK * FEAT];
__device__ float g_K[(size_t)T_TOK * FEAT];
__device__ float g_V[(size_t)T_TOK * FEAT];
__device__ float g_O[(size_t)T_TOK * FEAT];

// ---------------- NT SGEMM: C[M,N] = A[M,K] * B[N,K]^T (+bias[n]) ----------------
// A row-major K-contiguous, B row-major K-contiguous (weights [out,in]).
#define BM 128
#define BN 128
#define BKK 8

template <bool HAS_BIAS>
__global__ __launch_bounds__(256)
void sgemm_nt(const float* __restrict__ A,
              const float* __restrict__ B,
              const float* __restrict__ bias,
              float* __restrict__ C,
              int M, int N, int K)
{
    __shared__ float As[BKK][BM];
    __shared__ float Bs[BKK][BN];

    const int tid = threadIdx.x;
    const int m0  = blockIdx.y * BM;
    const int n0  = blockIdx.x * BN;

    // compute-phase thread tile: 16x16 threads, each 8x8 outputs
    const int tx = tid & 15;        // n direction
    const int ty = tid >> 4;        // m direction

    // loader mapping: 128 rows x 8 k  = 1024 floats = 256 x float4
    const int lr = tid >> 1;          // row 0..127
    const int lc = (tid & 1) * 4;     // k offset 0 or 4

    const float* Aptr = A + (size_t)(m0 + lr) * K + lc;
    const float* Bptr = B + (size_t)(n0 + lr) * K + lc;

    float acc[8][8];
#pragma unroll
    for (int i = 0; i < 8; i++)
#pragma unroll
        for (int j = 0; j < 8; j++) acc[i][j] = 0.0f;

    for (int k0 = 0; k0 < K; k0 += BKK) {
        float4 av = *(const float4*)(Aptr + k0);
        float4 bv = *(const float4*)(Bptr + k0);
        As[lc + 0][lr] = av.x;
        As[lc + 1][lr] = av.y;
        As[lc + 2][lr] = av.z;
        As[lc + 3][lr] = av.w;
        Bs[lc + 0][lr] = bv.x;
        Bs[lc + 1][lr] = bv.y;
        Bs[lc + 2][lr] = bv.z;
        Bs[lc + 3][lr] = bv.w;
        __syncthreads();

#pragma unroll
        for (int k = 0; k < BKK; k++) {
            float4 a0 = *(const float4*)&As[k][ty * 8];
            float4 a1 = *(const float4*)&As[k][ty * 8 + 4];
            float4 b0 = *(const float4*)&Bs[k][tx * 8];
            float4 b1 = *(const float4*)&Bs[k][tx * 8 + 4];
            float ra[8] = {a0.x, a0.y, a0.z, a0.w, a1.x, a1.y, a1.z, a1.w};
            float rb[8] = {b0.x, b0.y, b0.z, b0.w, b1.x, b1.y, b1.z, b1.w};
#pragma unroll
            for (int i = 0; i < 8; i++)
#pragma unroll
                for (int j = 0; j < 8; j++)
                    acc[i][j] = fmaf(ra[i], rb[j], acc[i][j]);
        }
        __syncthreads();
    }

    float bb[8];
#pragma unroll
    for (int j = 0; j < 8; j++)
        bb[j] = HAS_BIAS ? bias[n0 + tx * 8 + j] : 0.0f;

#pragma unroll
    for (int i = 0; i < 8; i++) {
        size_t m = (size_t)(m0 + ty * 8 + i);
        float* cp = C + m * N + n0 + tx * 8;
        float4 o0 = make_float4(acc[i][0] + bb[0], acc[i][1] + bb[1],
                                acc[i][2] + bb[2], acc[i][3] + bb[3]);
        float4 o1 = make_float4(acc[i][4] + bb[4], acc[i][5] + bb[5],
                                acc[i][6] + bb[6], acc[i][7] + bb[7]);
        *(float4*)cp       = o0;
        *(float4*)(cp + 4) = o1;
    }
}

// ---------------- per-token attention ----------------
// For token t:
//   S[c,d]   = (1/8) * sum_h K[t,h*64+c] * Q[t,h*64+d]        (64x64)
//   P        = softmax over d of S
//   O[t,h*64+d] = sum_v V[t,h*64+v] * P[v,d]
__global__ __launch_bounds__(256)
void attn_kernel(const float* __restrict__ Q,
                 const float* __restrict__ K,
                 const float* __restrict__ V,
                 float* __restrict__ O)
{
    __shared__ float sQ[FEAT];
    __shared__ float sK[FEAT];
    __shared__ float sV[FEAT];
    __shared__ float sS[KD * KD];   // 64x64

    const int t   = blockIdx.x;
    const int tid = threadIdx.x;
    const size_t base = (size_t)t * FEAT;

    // load Q,K,V for this token (256 float4 each)
    ((float4*)sQ)[tid] = ((const float4*)(Q + base))[tid];
    ((float4*)sK)[tid] = ((const float4*)(K + base))[tid];
    ((float4*)sV)[tid] = ((const float4*)(V + base))[tid];
    __syncthreads();

    const int d  = tid & 63;   // column (softmax axis)
    const int g4 = tid >> 6;   // 0..3

    // S: each thread handles column d, rows c = cc*4 + g4
    {
        float qreg[NHEAD];
#pragma unroll
        for (int h = 0; h < NHEAD; h++) qreg[h] = sQ[h * 64 + d];
#pragma unroll
        for (int cc = 0; cc < 16; cc++) {
            int c = cc * 4 + g4;
            float s = 0.0f;
#pragma unroll
            for (int h = 0; h < NHEAD; h++)
                s = fmaf(sK[h * 64 + c], qreg[h], s);
            sS[c * 64 + d] = s * 0.125f;
        }
    }
    __syncthreads();

    // softmax over d for each row c; 4 threads per row (shuffle groups of 4)
    {
        const int row = tid >> 2;
        const int j   = tid & 3;
        float* Srow = sS + row * 64;
        float mx = -1e30f;
#pragma unroll
        for (int i = 0; i < 16; i++) mx = fmaxf(mx, Srow[j + 4 * i]);
        mx = fmaxf(mx, __shfl_xor_sync(0xffffffffu, mx, 1));
        mx = fmaxf(mx, __shfl_xor_sync(0xffffffffu, mx, 2));
        float sum = 0.0f;
#pragma unroll
        for (int i = 0; i < 16; i++) {
            float e = __expf(Srow[j + 4 * i] - mx);
            Srow[j + 4 * i] = e;
            sum += e;
        }
        sum += __shfl_xor_sync(0xffffffffu, sum, 1);
        sum += __shfl_xor_sync(0xffffffffu, sum, 2);
        float inv = 1.0f / sum;
#pragma unroll
        for (int i = 0; i < 16; i++) Srow[j + 4 * i] *= inv;
    }
    __syncthreads();

    // O: thread handles column d, heads h = i*4 + g4
    {
        float accv[4] = {0.f, 0.f, 0.f, 0.f};
#pragma unroll 16
        for (int v = 0; v < 64; v++) {
            float p = sS[v * 64 + d];
#pragma unroll
            for (int i = 0; i < 4; i++)
                accv[i] = fmaf(sV[(i * 4 + g4) * 64 + v], p, accv[i]);
        }
        float* o = O + base;
#pragma unroll
        for (int i = 0; i < 4; i++)
            o[(i * 4 + g4) * 64 + d] = accv[i];
    }
}

// ---------------- launch ----------------
extern "C" void kernel_launch(void* const* d_in, const int* in_sizes, int n_in,
                              void* d_out, int out_size)
{
    const float* x1 = (const float*)d_in[0];
    const float* x2 = (const float*)d_in[1];
    const float* Wq = (const float*)d_in[2];
    const float* Wk = (const float*)d_in[3];
    const float* Wv = (const float*)d_in[4];
    const float* Wo = (const float*)d_in[5];
    const float* bo = (const float*)d_in[6];
    float* out = (float*)d_out;

    float *Qp, *Kp, *Vp, *Op;
    cudaGetSymbolAddress((void**)&Qp, g_Q);
    cudaGetSymbolAddress((void**)&Kp, g_K);
    cudaGetSymbolAddress((void**)&Vp, g_V);
    cudaGetSymbolAddress((void**)&Op, g_O);

    dim3 grid(FEAT / BN, T_TOK / BM);   // (8, 128)
    sgemm_nt<false><<<grid, 256>>>(x1, Wq, nullptr, Qp, T_TOK, FEAT, FEAT);
    sgemm_nt<false><<<grid, 256>>>(x2, Wk, nullptr, Kp, T_TOK, FEAT, FEAT);
    sgemm_nt<false><<<grid, 256>>>(x2, Wv, nullptr, Vp, T_TOK, FEAT, FEAT);

    attn_kernel<<<T_TOK, 256>>>(Qp, Kp, Vp, Op);

    sgemm_nt<true><<<grid, 256>>>(Op, Wo, bo, out, T_TOK, FEAT, FEAT);
}

// round 5
// speedup vs baseline: 2.3659x; 2.3659x over previous
#include <cuda_runtime.h>
#include <cuda_bf16.h>
#include <cstdint>
#include <math.h>

// ---------------- problem constants ----------------
#define T_TOK   16384     // B*M = 8*2048
#define FEAT    1024
#define NHEAD   16
#define KD      64

// ---------------- device scratch (no cudaMalloc allowed) ----------------
__device__ __nv_bfloat16 g_x1h[(size_t)T_TOK * FEAT];
__device__ __nv_bfloat16 g_x1l[(size_t)T_TOK * FEAT];
__device__ __nv_bfloat16 g_x2h[(size_t)T_TOK * FEAT];
__device__ __nv_bfloat16 g_x2l[(size_t)T_TOK * FEAT];
__device__ __nv_bfloat16 g_Ohh[(size_t)T_TOK * FEAT];
__device__ __nv_bfloat16 g_Oll[(size_t)T_TOK * FEAT];
__device__ __nv_bfloat16 g_Wqh[(size_t)FEAT * FEAT];
__device__ __nv_bfloat16 g_Wql[(size_t)FEAT * FEAT];
__device__ __nv_bfloat16 g_Wkh[(size_t)FEAT * FEAT];
__device__ __nv_bfloat16 g_Wkl[(size_t)FEAT * FEAT];
__device__ __nv_bfloat16 g_Wvh[(size_t)FEAT * FEAT];
__device__ __nv_bfloat16 g_Wvl[(size_t)FEAT * FEAT];
__device__ __nv_bfloat16 g_Woh[(size_t)FEAT * FEAT];
__device__ __nv_bfloat16 g_Wol[(size_t)FEAT * FEAT];
__device__ float g_Q[(size_t)T_TOK * FEAT];
__device__ float g_K[(size_t)T_TOK * FEAT];
__device__ float g_V[(size_t)T_TOK * FEAT];

// ---------------- low-level helpers (sm_80+ baseline PTX only) ----------------
__device__ __forceinline__ uint32_t smem_u32(const void* p) {
    uint32_t a;
    asm("{ .reg .u64 t; cvta.to.shared.u64 t, %1; cvt.u32.u64 %0, t; }" : "=r"(a) : "l"(p));
    return a;
}
#define CP16(dst, src) \
    asm volatile("cp.async.cg.shared.global [%0], [%1], 16;" :: "r"(dst), "l"(src))
#define CP_COMMIT() asm volatile("cp.async.commit_group;" ::: "memory")
#define CP_WAIT1()  asm volatile("cp.async.wait_group 1;"  ::: "memory")

__device__ __forceinline__ void ldsm4(uint32_t a[4], uint32_t addr) {
    asm volatile("ldmatrix.sync.aligned.m8n8.x4.shared.b16 {%0,%1,%2,%3}, [%4];"
                 : "=r"(a[0]), "=r"(a[1]), "=r"(a[2]), "=r"(a[3]) : "r"(addr));
}
__device__ __forceinline__ void mma16816(float c[4], const uint32_t a[4],
                                         uint32_t b0, uint32_t b1) {
    asm volatile(
        "mma.sync.aligned.m16n8k16.row.col.f32.bf16.bf16.f32 "
        "{%0,%1,%2,%3}, {%4,%5,%6,%7}, {%8,%9}, {%0,%1,%2,%3};"
        : "+f"(c[0]), "+f"(c[1]), "+f"(c[2]), "+f"(c[3])
        : "r"(a[0]), "r"(a[1]), "r"(a[2]), "r"(a[3]), "r"(b0), "r"(b1));
}

// ---------------- fp32 -> bf16 hi/lo split ----------------
__global__ __launch_bounds__(256)
void split_kernel(const float* __restrict__ src, __nv_bfloat16* __restrict__ hi,
                  __nv_bfloat16* __restrict__ lo, int n4) {
    int i = blockIdx.x * blockDim.x + threadIdx.x;
    if (i >= n4) return;
    float4 v = ((const float4*)src)[i];
    __nv_bfloat16 h0 = __float2bfloat16_rn(v.x);
    __nv_bfloat16 h1 = __float2bfloat16_rn(v.y);
    __nv_bfloat16 h2 = __float2bfloat16_rn(v.z);
    __nv_bfloat16 h3 = __float2bfloat16_rn(v.w);
    __nv_bfloat16 l0 = __float2bfloat16_rn(v.x - __bfloat162float(h0));
    __nv_bfloat16 l1 = __float2bfloat16_rn(v.y - __bfloat162float(h1));
    __nv_bfloat16 l2 = __float2bfloat16_rn(v.z - __bfloat162float(h2));
    __nv_bfloat16 l3 = __float2bfloat16_rn(v.w - __bfloat162float(h3));
    ((__nv_bfloat162*)hi)[2 * i]     = __nv_bfloat162(h0, h1);
    ((__nv_bfloat162*)hi)[2 * i + 1] = __nv_bfloat162(h2, h3);
    ((__nv_bfloat162*)lo)[2 * i]     = __nv_bfloat162(l0, l1);
    ((__nv_bfloat162*)lo)[2 * i + 1] = __nv_bfloat162(l2, l3);
}

// ---------------- mma.sync split-bf16 NT GEMM ----------------
// C[M,N] = (Ah+Al)[M,K] * (Bh+Bl)[N,K]^T (+bias), fp32 out.
// CTA tile 128x128, 8 warps (warp tile 32x64), K staged by 64, double buffered.
#define KC      64                       // k elements per stage
#define ROWB    144                      // 128 data bytes padded to 144 (9x16B)
#define TILEB   (128 * ROWB)             // 18432 B per matrix tile
#define STAGEB  (4 * TILEB)              // Ah, Al, Bh, Bl
#define GSMEM   (2 * STAGEB)             // 147456 B
#define NSTAGES (FEAT / KC)              // 16

__device__ __forceinline__ void load_stage(
    const __nv_bfloat16* __restrict__ Ah, const __nv_bfloat16* __restrict__ Al,
    const __nv_bfloat16* __restrict__ Bh, const __nv_bfloat16* __restrict__ Bl,
    int m0, int n0, int k0, uint32_t sb, int tid)
{
#pragma unroll
    for (int i = 0; i < 4; i++) {
        int idx = i * 256 + tid;          // 0..1023
        int row = idx >> 3;               // 0..127
        int ch  = idx & 7;                // 16B chunk within 128B row
        uint32_t so = (uint32_t)(row * ROWB + ch * 16);
        size_t ga = (size_t)(m0 + row) * FEAT + k0 + ch * 8;
        size_t gb = (size_t)(n0 + row) * FEAT + k0 + ch * 8;
        CP16(sb + so,              (const char*)(Ah + ga));
        CP16(sb + TILEB + so,      (const char*)(Al + ga));
        CP16(sb + 2 * TILEB + so,  (const char*)(Bh + gb));
        CP16(sb + 3 * TILEB + so,  (const char*)(Bl + gb));
    }
}

template <bool HAS_BIAS>
__global__ __launch_bounds__(256, 1)
void gemm_tc(const __nv_bfloat16* __restrict__ Ah, const __nv_bfloat16* __restrict__ Al,
             const __nv_bfloat16* __restrict__ Bh, const __nv_bfloat16* __restrict__ Bl,
             const float* __restrict__ bias, float* __restrict__ C)
{
    extern __shared__ char dsm[];
    const int tid  = threadIdx.x;
    const int lane = tid & 31;
    const int wid  = tid >> 5;
    const int wm   = wid & 3;          // m block (32 rows)
    const int wn   = wid >> 2;         // n block (64 cols)
    const int m0   = blockIdx.y * 128;
    const int n0   = blockIdx.x * 128;

    const uint32_t smem = smem_u32(dsm);

    // ldmatrix lane addressing: lanes 0-7 -> rows 0-7, 8-15 -> rows 8-15,
    // 16-23 -> rows 0-7 (+16B), 24-31 -> rows 8-15 (+16B)
    const int lrow = lane & 15;
    const int lch  = lane >> 4;
    const uint32_t aoff = (uint32_t)((wm * 32 + lrow) * ROWB + lch * 16);
    const uint32_t boff = (uint32_t)((wn * 64 + lrow) * ROWB + lch * 16);

    float acc[2][8][4];
#pragma unroll
    for (int i = 0; i < 2; i++)
#pragma unroll
        for (int j = 0; j < 8; j++)
#pragma unroll
            for (int q = 0; q < 4; q++) acc[i][j][q] = 0.0f;

    // prologue: stages 0 and 1
    load_stage(Ah, Al, Bh, Bl, m0, n0, 0, smem, tid);
    CP_COMMIT();
    load_stage(Ah, Al, Bh, Bl, m0, n0, KC, smem + STAGEB, tid);
    CP_COMMIT();

    for (int c = 0; c < NSTAGES; c++) {
        CP_WAIT1();
        __syncthreads();

        const uint32_t sb  = smem + (uint32_t)(c & 1) * STAGEB;
        const uint32_t aHi = sb + aoff;
        const uint32_t aLo = sb + TILEB + aoff;
        const uint32_t bHi = sb + 2 * TILEB + boff;
        const uint32_t bLo = sb + 3 * TILEB + boff;

#pragma unroll
        for (int ks = 0; ks < KC / 16; ks++) {
            const uint32_t ko = (uint32_t)(ks * 32);   // 16 bf16 = 32 B
            uint32_t ah[2][4], al[2][4], bb[4][4];
#pragma unroll
            for (int mf = 0; mf < 2; mf++) ldsm4(ah[mf], aHi + mf * (16 * ROWB) + ko);
#pragma unroll
            for (int mf = 0; mf < 2; mf++) ldsm4(al[mf], aLo + mf * (16 * ROWB) + ko);
            // B hi: (Ah,Bh) and (Al,Bh)
#pragma unroll
            for (int nt = 0; nt < 4; nt++) ldsm4(bb[nt], bHi + nt * (16 * ROWB) + ko);
#pragma unroll
            for (int mf = 0; mf < 2; mf++)
#pragma unroll
                for (int nt = 0; nt < 4; nt++) {
                    mma16816(acc[mf][nt * 2],     ah[mf], bb[nt][0], bb[nt][2]);
                    mma16816(acc[mf][nt * 2 + 1], ah[mf], bb[nt][1], bb[nt][3]);
                }
#pragma unroll
            for (int mf = 0; mf < 2; mf++)
#pragma unroll
                for (int nt = 0; nt < 4; nt++) {
                    mma16816(acc[mf][nt * 2],     al[mf], bb[nt][0], bb[nt][2]);
                    mma16816(acc[mf][nt * 2 + 1], al[mf], bb[nt][1], bb[nt][3]);
                }
            // B lo: (Ah,Bl)
#pragma unroll
            for (int nt = 0; nt < 4; nt++) ldsm4(bb[nt], bLo + nt * (16 * ROWB) + ko);
#pragma unroll
            for (int mf = 0; mf < 2; mf++)
#pragma unroll
                for (int nt = 0; nt < 4; nt++) {
                    mma16816(acc[mf][nt * 2],     ah[mf], bb[nt][0], bb[nt][2]);
                    mma16816(acc[mf][nt * 2 + 1], ah[mf], bb[nt][1], bb[nt][3]);
                }
        }

        __syncthreads();
        if (c + 2 < NSTAGES)
            load_stage(Ah, Al, Bh, Bl, m0, n0, (c + 2) * KC,
                       smem + (uint32_t)(c & 1) * STAGEB, tid);
        CP_COMMIT();   // empty group when no load keeps wait_group bookkeeping uniform
    }

    // epilogue: direct fp32 stores (2 floats/thread/frag)
    const int rbase = m0 + wm * 32 + (lane >> 2);
    const int cbase = n0 + wn * 64 + (lane & 3) * 2;
#pragma unroll
    for (int mf = 0; mf < 2; mf++) {
#pragma unroll
        for (int nf = 0; nf < 8; nf++) {
            int r = rbase + mf * 16;
            int cc = cbase + nf * 8;
            float b0 = 0.f, b1 = 0.f;
            if (HAS_BIAS) { b0 = bias[cc]; b1 = bias[cc + 1]; }
            float* p0 = C + (size_t)r * FEAT + cc;
            p0[0] = acc[mf][nf][0] + b0;
            p0[1] = acc[mf][nf][1] + b1;
            float* p1 = C + (size_t)(r + 8) * FEAT + cc;
            p1[0] = acc[mf][nf][2] + b0;
            p1[1] = acc[mf][nf][3] + b1;
        }
    }
}

// ---------------- per-token attention (fp32; outputs split bf16) ----------------
__global__ __launch_bounds__(256)
void attn_kernel(const float* __restrict__ Q,
                 const float* __restrict__ K,
                 const float* __restrict__ V,
                 __nv_bfloat16* __restrict__ Oh,
                 __nv_bfloat16* __restrict__ Ol)
{
    __shared__ float sQ[FEAT];
    __shared__ float sK[FEAT];
    __shared__ float sV[FEAT];
    __shared__ float sS[KD * 65];   // padded stride 65: conflict-free softmax

    const int t   = blockIdx.x;
    const int tid = threadIdx.x;
    const size_t base = (size_t)t * FEAT;

    ((float4*)sQ)[tid] = ((const float4*)(Q + base))[tid];
    ((float4*)sK)[tid] = ((const float4*)(K + base))[tid];
    ((float4*)sV)[tid] = ((const float4*)(V + base))[tid];
    __syncthreads();

    const int d  = tid & 63;
    const int g4 = tid >> 6;

    {
        float qreg[NHEAD];
#pragma unroll
        for (int h = 0; h < NHEAD; h++) qreg[h] = sQ[h * 64 + d];
#pragma unroll
        for (int cc = 0; cc < 16; cc++) {
            int c = cc * 4 + g4;
            float s = 0.0f;
#pragma unroll
            for (int h = 0; h < NHEAD; h++)
                s = fmaf(sK[h * 64 + c], qreg[h], s);
            sS[c * 65 + d] = s * 0.125f;
        }
    }
    __syncthreads();

    {
        const int row = tid >> 2;
        const int j   = tid & 3;
        float* Srow = sS + row * 65;
        float mx = -1e30f;
#pragma unroll
        for (int i = 0; i < 16; i++) mx = fmaxf(mx, Srow[j + 4 * i]);
        mx = fmaxf(mx, __shfl_xor_sync(0xffffffffu, mx, 1));
        mx = fmaxf(mx, __shfl_xor_sync(0xffffffffu, mx, 2));
        float sum = 0.0f;
#pragma unroll
        for (int i = 0; i < 16; i++) {
            float e = __expf(Srow[j + 4 * i] - mx);
            Srow[j + 4 * i] = e;
            sum += e;
        }
        sum += __shfl_xor_sync(0xffffffffu, sum, 1);
        sum += __shfl_xor_sync(0xffffffffu, sum, 2);
        float inv = 1.0f / sum;
#pragma unroll
        for (int i = 0; i < 16; i++) Srow[j + 4 * i] *= inv;
    }
    __syncthreads();

    {
        float accv[4] = {0.f, 0.f, 0.f, 0.f};
#pragma unroll 16
        for (int v = 0; v < 64; v++) {
            float p = sS[v * 65 + d];
#pragma unroll
            for (int i = 0; i < 4; i++)
                accv[i] = fmaf(sV[(i * 4 + g4) * 64 + v], p, accv[i]);
        }
#pragma unroll
        for (int i = 0; i < 4; i++) {
            size_t idx = base + (size_t)(i * 4 + g4) * 64 + d;
            float a = accv[i];
            __nv_bfloat16 h = __float2bfloat16_rn(a);
            __nv_bfloat16 l = __float2bfloat16_rn(a - __bfloat162float(h));
            Oh[idx] = h;
            Ol[idx] = l;
        }
    }
}

// ---------------- launch ----------------
extern "C" void kernel_launch(void* const* d_in, const int* in_sizes, int n_in,
                              void* d_out, int out_size)
{
    const float* x1 = (const float*)d_in[0];
    const float* x2 = (const float*)d_in[1];
    const float* Wq = (const float*)d_in[2];
    const float* Wk = (const float*)d_in[3];
    const float* Wv = (const float*)d_in[4];
    const float* Wo = (const float*)d_in[5];
    const float* bo = (const float*)d_in[6];
    float* out = (float*)d_out;

    __nv_bfloat16 *x1h, *x1l, *x2h, *x2l, *Ohp, *Olp;
    __nv_bfloat16 *Wqh, *Wql, *Wkh, *Wkl, *Wvh, *Wvl, *Woh, *Wol;
    float *Qp, *Kp, *Vp;
    cudaGetSymbolAddress((void**)&x1h, g_x1h);
    cudaGetSymbolAddress((void**)&x1l, g_x1l);
    cudaGetSymbolAddress((void**)&x2h, g_x2h);
    cudaGetSymbolAddress((void**)&x2l, g_x2l);
    cudaGetSymbolAddress((void**)&Ohp, g_Ohh);
    cudaGetSymbolAddress((void**)&Olp, g_Oll);
    cudaGetSymbolAddress((void**)&Wqh, g_Wqh);
    cudaGetSymbolAddress((void**)&Wql, g_Wql);
    cudaGetSymbolAddress((void**)&Wkh, g_Wkh);
    cudaGetSymbolAddress((void**)&Wkl, g_Wkl);
    cudaGetSymbolAddress((void**)&Wvh, g_Wvh);
    cudaGetSymbolAddress((void**)&Wvl, g_Wvl);
    cudaGetSymbolAddress((void**)&Woh, g_Woh);
    cudaGetSymbolAddress((void**)&Wol, g_Wol);
    cudaGetSymbolAddress((void**)&Qp, g_Q);
    cudaGetSymbolAddress((void**)&Kp, g_K);
    cudaGetSymbolAddress((void**)&Vp, g_V);

    cudaFuncSetAttribute(gemm_tc<false>, cudaFuncAttributeMaxDynamicSharedMemorySize, GSMEM);
    cudaFuncSetAttribute(gemm_tc<true>,  cudaFuncAttributeMaxDynamicSharedMemorySize, GSMEM);

    const int nTok4 = T_TOK * FEAT / 4;
    const int nW4   = FEAT * FEAT / 4;
    split_kernel<<<(nTok4 + 255) / 256, 256>>>(x1, x1h, x1l, nTok4);
    split_kernel<<<(nTok4 + 255) / 256, 256>>>(x2, x2h, x2l, nTok4);
    split_kernel<<<(nW4 + 255) / 256, 256>>>(Wq, Wqh, Wql, nW4);
    split_kernel<<<(nW4 + 255) / 256, 256>>>(Wk, Wkh, Wkl, nW4);
    split_kernel<<<(nW4 + 255) / 256, 256>>>(Wv, Wvh, Wvl, nW4);
    split_kernel<<<(nW4 + 255) / 256, 256>>>(Wo, Woh, Wol, nW4);

    dim3 grid(FEAT / 128, T_TOK / 128);   // (8, 128)
    gemm_tc<false><<<grid, 256, GSMEM>>>(x1h, x1l, Wqh, Wql, nullptr, Qp);
    gemm_tc<false><<<grid, 256, GSMEM>>>(x2h, x2l, Wkh, Wkl, nullptr, Kp);
    gemm_tc<false><<<grid, 256, GSMEM>>>(x2h, x2l, Wvh, Wvl, nullptr, Vp);

    attn_kernel<<<T_TOK, 256>>>(Qp, Kp, Vp, Ohp, Olp);

    gemm_tc<true><<<grid, 256, GSMEM>>>(Ohp, Olp, Woh, Wol, bo, out);
}